// round 3
// baseline (speedup 1.0000x reference)
#include <cuda_runtime.h>
#include <cstddef>

#define NN   20000
#define EE   320000
#define ELL  100000
#define ET   (EE + NN)          // 340000 edges incl. self loops
#define INF_ 256
#define HIDC 128
#define OUTC 128
#define HH   4
#define C1   (HH * HIDC)        // 512

// ---------------- scratch (device globals: allocation-free) ----------------
__device__ float g_xl1[(size_t)NN * C1];
__device__ float g_xr1[(size_t)NN * C1];
__device__ float g_out1[(size_t)NN * C1];       // agg -> z1 (gelu in-place)
__device__ float g_logits1[(size_t)ET * HH];    // logits, then exp(logit-max)
__device__ int   g_max1[NN * HH];
__device__ float g_sum1[NN * HH];
__device__ float g_xl2[(size_t)NN * OUTC];
__device__ float g_xr2[(size_t)NN * OUTC];
__device__ float g_out2[(size_t)NN * OUTC];     // agg -> z2
__device__ float g_logits2[ET];
__device__ int   g_max2[NN];
__device__ float g_sum2[NN];
__device__ float g_h[(size_t)ELL * HIDC];       // decoder hidden (post-gelu)

// ---------------- helpers ----------------
__device__ __forceinline__ float lrelu(float x) { return x >= 0.f ? x : 0.2f * x; }

__device__ __forceinline__ float gelu_t(float x) {
    // JAX default gelu (approximate=True, tanh form)
    float x3 = x * x * x;
    return 0.5f * x * (1.f + tanhf(0.7978845608028654f * (x + 0.044715f * x3)));
}

__device__ __forceinline__ int fkey(float f) {
    int i = __float_as_int(f);
    return i >= 0 ? i : (i ^ 0x7fffffff);
}
__device__ __forceinline__ float keyf(int i) {
    return __int_as_float(i >= 0 ? i : (i ^ 0x7fffffff));
}

__device__ __forceinline__ void red_add_v4(float* p, float4 v) {
    asm volatile("red.global.add.v4.f32 [%0], {%1,%2,%3,%4};"
                 :: "l"(p), "f"(v.x), "f"(v.y), "f"(v.z), "f"(v.w) : "memory");
}

// ---------------- init (every launch: zero accumulators, -inf maxes) -------
__global__ void init_kernel() {
    int i = blockIdx.x * blockDim.x + threadIdx.x;
    if (i < NN * C1)   g_out1[i] = 0.f;
    if (i < NN * OUTC) g_out2[i] = 0.f;
    if (i < NN * HH) { g_max1[i] = (int)0x80000000; g_sum1[i] = 0.f; }
    if (i < NN)      { g_max2[i] = (int)0x80000000; g_sum2[i] = 0.f; }
}

// ---------------- GEMM: C{0,1} = A @ B{0,1} + bias{0,1} --------------------
// 128x128 tile, BK=8, 256 threads, 8x8 per thread. grid.x = 2*(Nc/128),
// first half computes matrix 0, second half matrix 1 (shared A).
__global__ __launch_bounds__(256) void gemm_dual(
    const float* __restrict__ A,
    const float* __restrict__ B0, const float* __restrict__ B1,
    const float* __restrict__ bias0, const float* __restrict__ bias1,
    float* __restrict__ C0, float* __restrict__ C1p,
    int M, int K, int Nc)
{
    __shared__ float As[8][128];
    __shared__ float Bs[8][128];

    int nb  = Nc >> 7;
    int mat = (blockIdx.x >= nb) ? 1 : 0;
    int bn  = (blockIdx.x - mat * nb) << 7;
    int bm  = blockIdx.y << 7;

    const float* B    = mat ? B1 : B0;
    const float* bias = mat ? bias1 : bias0;
    float*       C    = mat ? C1p : C0;

    int tid   = threadIdx.x;
    int a_row = tid >> 1;
    int a_col = (tid & 1) << 2;
    int b_row = tid >> 5;
    int b_col = (tid & 31) << 2;
    int ty = tid >> 4, tx = tid & 15;

    float acc[8][8];
#pragma unroll
    for (int i = 0; i < 8; i++)
#pragma unroll
        for (int j = 0; j < 8; j++) acc[i][j] = 0.f;

    bool a_ok = (bm + a_row) < M;
    const float* Aptr = A + (size_t)(bm + a_row) * K + a_col;
    const float* Bptr = B + (size_t)b_row * Nc + bn + b_col;

    for (int k0 = 0; k0 < K; k0 += 8) {
        float4 av = a_ok ? *(const float4*)(Aptr + k0) : make_float4(0.f, 0.f, 0.f, 0.f);
        float4 bv = *(const float4*)(Bptr + (size_t)k0 * Nc);
        As[a_col + 0][a_row] = av.x;
        As[a_col + 1][a_row] = av.y;
        As[a_col + 2][a_row] = av.z;
        As[a_col + 3][a_row] = av.w;
        *(float4*)&Bs[b_row][b_col] = bv;
        __syncthreads();
#pragma unroll
        for (int kk = 0; kk < 8; kk++) {
            float4 a0 = *(const float4*)&As[kk][ty * 8];
            float4 a1 = *(const float4*)&As[kk][ty * 8 + 4];
            float4 b0 = *(const float4*)&Bs[kk][tx * 8];
            float4 b1 = *(const float4*)&Bs[kk][tx * 8 + 4];
            float a[8] = {a0.x, a0.y, a0.z, a0.w, a1.x, a1.y, a1.z, a1.w};
            float b[8] = {b0.x, b0.y, b0.z, b0.w, b1.x, b1.y, b1.z, b1.w};
#pragma unroll
            for (int i = 0; i < 8; i++)
#pragma unroll
                for (int j = 0; j < 8; j++) acc[i][j] += a[i] * b[j];
        }
        __syncthreads();
    }

    float4 bi0 = *(const float4*)(bias + bn + tx * 8);
    float4 bi1 = *(const float4*)(bias + bn + tx * 8 + 4);
#pragma unroll
    for (int i = 0; i < 8; i++) {
        int row = bm + ty * 8 + i;
        if (row >= M) continue;
        float* cp = C + (size_t)row * Nc + bn + tx * 8;
        float4 o0 = make_float4(acc[i][0] + bi0.x, acc[i][1] + bi0.y,
                                acc[i][2] + bi0.z, acc[i][3] + bi0.w);
        float4 o1 = make_float4(acc[i][4] + bi1.x, acc[i][5] + bi1.y,
                                acc[i][6] + bi1.z, acc[i][7] + bi1.w);
        *(float4*)cp       = o0;
        *(float4*)(cp + 4) = o1;
    }
}

// ---------------- decoder GEMM: H = gelu([z2[a]|z2[b]] @ Wd1 + bd1) --------
// M=ELL, K=256, Nc=128; A rows gathered on the fly.
__global__ __launch_bounds__(256) void gemm_dec(
    const float* __restrict__ z2, const int* __restrict__ eli,
    const float* __restrict__ Wd1, const float* __restrict__ bd1)
{
    __shared__ float As[8][128];
    __shared__ float Bs[8][128];

    const int M = ELL, K = 2 * OUTC, Nc = HIDC;
    int bm = blockIdx.y << 7;

    int tid   = threadIdx.x;
    int a_row = tid >> 1;
    int a_col = (tid & 1) << 2;
    int b_row = tid >> 5;
    int b_col = (tid & 31) << 2;
    int ty = tid >> 4, tx = tid & 15;

    float acc[8][8];
#pragma unroll
    for (int i = 0; i < 8; i++)
#pragma unroll
        for (int j = 0; j < 8; j++) acc[i][j] = 0.f;

    int gr = bm + a_row;
    bool a_ok = gr < M;
    int n0 = a_ok ? eli[gr] : 0;
    int n1 = a_ok ? eli[ELL + gr] : 0;
    const float* Bptr = Wd1 + (size_t)b_row * Nc + b_col;

    for (int k0 = 0; k0 < K; k0 += 8) {
        int kk = k0 + a_col;
        const float* src = z2 + (size_t)(kk < OUTC ? n0 : n1) * OUTC + (kk & (OUTC - 1));
        float4 av = a_ok ? *(const float4*)src : make_float4(0.f, 0.f, 0.f, 0.f);
        float4 bv = *(const float4*)(Bptr + (size_t)k0 * Nc);
        As[a_col + 0][a_row] = av.x;
        As[a_col + 1][a_row] = av.y;
        As[a_col + 2][a_row] = av.z;
        As[a_col + 3][a_row] = av.w;
        *(float4*)&Bs[b_row][b_col] = bv;
        __syncthreads();
#pragma unroll
        for (int kq = 0; kq < 8; kq++) {
            float4 a0 = *(const float4*)&As[kq][ty * 8];
            float4 a1 = *(const float4*)&As[kq][ty * 8 + 4];
            float4 b0 = *(const float4*)&Bs[kq][tx * 8];
            float4 b1 = *(const float4*)&Bs[kq][tx * 8 + 4];
            float a[8] = {a0.x, a0.y, a0.z, a0.w, a1.x, a1.y, a1.z, a1.w};
            float b[8] = {b0.x, b0.y, b0.z, b0.w, b1.x, b1.y, b1.z, b1.w};
#pragma unroll
            for (int i = 0; i < 8; i++)
#pragma unroll
                for (int j = 0; j < 8; j++) acc[i][j] += a[i] * b[j];
        }
        __syncthreads();
    }

    float4 bi0 = *(const float4*)(bd1 + tx * 8);
    float4 bi1 = *(const float4*)(bd1 + tx * 8 + 4);
#pragma unroll
    for (int i = 0; i < 8; i++) {
        int row = bm + ty * 8 + i;
        if (row >= M) continue;
        float* cp = g_h + (size_t)row * Nc + tx * 8;
        float4 o0 = make_float4(gelu_t(acc[i][0] + bi0.x), gelu_t(acc[i][1] + bi0.y),
                                gelu_t(acc[i][2] + bi0.z), gelu_t(acc[i][3] + bi0.w));
        float4 o1 = make_float4(gelu_t(acc[i][4] + bi1.x), gelu_t(acc[i][5] + bi1.y),
                                gelu_t(acc[i][6] + bi1.z), gelu_t(acc[i][7] + bi1.w));
        *(float4*)cp       = o0;
        *(float4*)(cp + 4) = o1;
    }
}

// ---------------- layer 1 edge kernels (H=4, C=128) ------------------------
__global__ __launch_bounds__(256) void logits1_kernel(const int* __restrict__ ei,
                                                      const float* __restrict__ att)
{
    int gw = (blockIdx.x * blockDim.x + threadIdx.x) >> 5;
    if (gw >= ET) return;
    int lane = threadIdx.x & 31;
    int src, dst;
    if (gw < EE) { src = ei[gw]; dst = ei[EE + gw]; }
    else         { src = dst = gw - EE; }

    const float4* pl = (const float4*)(g_xl1 + (size_t)src * C1);
    const float4* pr = (const float4*)(g_xr1 + (size_t)dst * C1);
    const float4* pa = (const float4*)att;

    float res[HH];
#pragma unroll
    for (int h = 0; h < HH; h++) {
        int f = h * 32 + lane;
        float4 l = pl[f], r = pr[f], a = pa[f];
        float p = lrelu(l.x + r.x) * a.x + lrelu(l.y + r.y) * a.y +
                  lrelu(l.z + r.z) * a.z + lrelu(l.w + r.w) * a.w;
        p += __shfl_down_sync(0xffffffffu, p, 16);
        p += __shfl_down_sync(0xffffffffu, p, 8);
        p += __shfl_down_sync(0xffffffffu, p, 4);
        p += __shfl_down_sync(0xffffffffu, p, 2);
        p += __shfl_down_sync(0xffffffffu, p, 1);
        res[h] = p;
    }
    if (lane == 0) {
#pragma unroll
        for (int h = 0; h < HH; h++) {
            g_logits1[(size_t)gw * HH + h] = res[h];
            atomicMax(&g_max1[dst * HH + h], fkey(res[h]));
        }
    }
}

__global__ __launch_bounds__(256) void expsum1_kernel(const int* __restrict__ ei)
{
    int idx = blockIdx.x * blockDim.x + threadIdx.x;
    if (idx >= ET * HH) return;
    int e = idx >> 2, h = idx & 3;
    int dst = (e < EE) ? ei[EE + e] : e - EE;
    float m = keyf(g_max1[dst * HH + h]);
    float a = __expf(g_logits1[idx] - m);
    g_logits1[idx] = a;
    atomicAdd(&g_sum1[dst * HH + h], a);
}

__global__ __launch_bounds__(256) void scatter1_kernel(const int* __restrict__ ei)
{
    int gw = (blockIdx.x * blockDim.x + threadIdx.x) >> 5;
    if (gw >= ET) return;
    int lane = threadIdx.x & 31;
    int src, dst;
    if (gw < EE) { src = ei[gw]; dst = ei[EE + gw]; }
    else         { src = dst = gw - EE; }

    const float4* pl = (const float4*)(g_xl1 + (size_t)src * C1);
    float* pd = g_out1 + (size_t)dst * C1;
#pragma unroll
    for (int h = 0; h < HH; h++) {
        float alpha = g_logits1[(size_t)gw * HH + h] / g_sum1[dst * HH + h];
        int f = h * 32 + lane;
        float4 v = pl[f];
        v.x *= alpha; v.y *= alpha; v.z *= alpha; v.w *= alpha;
        red_add_v4(pd + f * 4, v);
    }
}

__global__ __launch_bounds__(256) void gelu1_kernel(const float* __restrict__ bias1)
{
    int i = blockIdx.x * blockDim.x + threadIdx.x;
    if (i >= NN * C1) return;
    g_out1[i] = gelu_t(g_out1[i] + bias1[i & (C1 - 1)]);
}

// ---------------- layer 2 edge kernels (H=1, C=128) ------------------------
__global__ __launch_bounds__(256) void logits2_kernel(const int* __restrict__ ei,
                                                      const float* __restrict__ att2)
{
    int gw = (blockIdx.x * blockDim.x + threadIdx.x) >> 5;
    if (gw >= ET) return;
    int lane = threadIdx.x & 31;
    int src, dst;
    if (gw < EE) { src = ei[gw]; dst = ei[EE + gw]; }
    else         { src = dst = gw - EE; }

    const float4* pl = (const float4*)(g_xl2 + (size_t)src * OUTC);
    const float4* pr = (const float4*)(g_xr2 + (size_t)dst * OUTC);
    float4 l = pl[lane], r = pr[lane], a = ((const float4*)att2)[lane];
    float p = lrelu(l.x + r.x) * a.x + lrelu(l.y + r.y) * a.y +
              lrelu(l.z + r.z) * a.z + lrelu(l.w + r.w) * a.w;
    p += __shfl_down_sync(0xffffffffu, p, 16);
    p += __shfl_down_sync(0xffffffffu, p, 8);
    p += __shfl_down_sync(0xffffffffu, p, 4);
    p += __shfl_down_sync(0xffffffffu, p, 2);
    p += __shfl_down_sync(0xffffffffu, p, 1);
    if (lane == 0) {
        g_logits2[gw] = p;
        atomicMax(&g_max2[dst], fkey(p));
    }
}

__global__ __launch_bounds__(256) void expsum2_kernel(const int* __restrict__ ei)
{
    int e = blockIdx.x * blockDim.x + threadIdx.x;
    if (e >= ET) return;
    int dst = (e < EE) ? ei[EE + e] : e - EE;
    float m = keyf(g_max2[dst]);
    float a = __expf(g_logits2[e] - m);
    g_logits2[e] = a;
    atomicAdd(&g_sum2[dst], a);
}

__global__ __launch_bounds__(256) void scatter2_kernel(const int* __restrict__ ei)
{
    int gw = (blockIdx.x * blockDim.x + threadIdx.x) >> 5;
    if (gw >= ET) return;
    int lane = threadIdx.x & 31;
    int src, dst;
    if (gw < EE) { src = ei[gw]; dst = ei[EE + gw]; }
    else         { src = dst = gw - EE; }

    float alpha = g_logits2[gw] / g_sum2[dst];
    const float4* pl = (const float4*)(g_xl2 + (size_t)src * OUTC);
    float4 v = pl[lane];
    v.x *= alpha; v.y *= alpha; v.z *= alpha; v.w *= alpha;
    red_add_v4(g_out2 + (size_t)dst * OUTC + lane * 4, v);
}

__global__ __launch_bounds__(256) void bias2_kernel(const float* __restrict__ bias2)
{
    int i = blockIdx.x * blockDim.x + threadIdx.x;
    if (i >= NN * OUTC) return;
    g_out2[i] += bias2[i & (OUTC - 1)];
}

// ---------------- decoder reduce: out = h . Wd2 + bd2 ----------------------
__global__ __launch_bounds__(256) void dec_reduce(const float* __restrict__ Wd2,
                                                  const float* __restrict__ bd2,
                                                  float* __restrict__ out)
{
    int m = (blockIdx.x * blockDim.x + threadIdx.x) >> 5;
    if (m >= ELL) return;
    int lane = threadIdx.x & 31;
    float4 h = *(const float4*)(g_h + (size_t)m * HIDC + lane * 4);
    float4 w = *(const float4*)(Wd2 + lane * 4);
    float p = h.x * w.x + h.y * w.y + h.z * w.z + h.w * w.w;
    p += __shfl_down_sync(0xffffffffu, p, 16);
    p += __shfl_down_sync(0xffffffffu, p, 8);
    p += __shfl_down_sync(0xffffffffu, p, 4);
    p += __shfl_down_sync(0xffffffffu, p, 2);
    p += __shfl_down_sync(0xffffffffu, p, 1);
    if (lane == 0) out[m] = p + bd2[0];
}

// ---------------- launch ----------------------------------------------------
extern "C" void kernel_launch(void* const* d_in, const int* in_sizes, int n_in,
                              void* d_out, int out_size)
{
    const float* x     = (const float*)d_in[0];
    const int*   ei    = (const int*)d_in[1];
    const int*   eli   = (const int*)d_in[2];
    const float* W_l1  = (const float*)d_in[3];
    const float* b_l1  = (const float*)d_in[4];
    const float* W_r1  = (const float*)d_in[5];
    const float* b_r1  = (const float*)d_in[6];
    const float* att1  = (const float*)d_in[7];
    const float* bias1 = (const float*)d_in[8];
    const float* W_l2  = (const float*)d_in[9];
    const float* b_l2  = (const float*)d_in[10];
    const float* W_r2  = (const float*)d_in[11];
    const float* b_r2  = (const float*)d_in[12];
    const float* att2  = (const float*)d_in[13];
    const float* bias2 = (const float*)d_in[14];
    const float* W_d1  = (const float*)d_in[15];
    const float* b_d1  = (const float*)d_in[16];
    const float* W_d2  = (const float*)d_in[17];
    const float* b_d2  = (const float*)d_in[18];
    float* out = (float*)d_out;

    float *xl1, *xr1, *out1, *xl2, *xr2, *out2;
    cudaGetSymbolAddress((void**)&xl1,  g_xl1);
    cudaGetSymbolAddress((void**)&xr1,  g_xr1);
    cudaGetSymbolAddress((void**)&out1, g_out1);
    cudaGetSymbolAddress((void**)&xl2,  g_xl2);
    cudaGetSymbolAddress((void**)&xr2,  g_xr2);
    cudaGetSymbolAddress((void**)&out2, g_out2);

    // 0) reset accumulators
    init_kernel<<<(NN * C1 + 255) / 256, 256>>>();

    // 1) layer-1 transforms: xl1 = x@W_l1+b_l1, xr1 = x@W_r1+b_r1
    {
        dim3 grid(2 * (C1 / 128), (NN + 127) / 128);
        gemm_dual<<<grid, 256>>>(x, W_l1, W_r1, b_l1, b_r1, xl1, xr1, NN, INF_, C1);
    }

    // 2) layer-1 attention
    int eb = ( (ET * 32) + 255 ) / 256;
    logits1_kernel<<<eb, 256>>>(ei, att1);
    expsum1_kernel<<<(ET * HH + 255) / 256, 256>>>(ei);
    scatter1_kernel<<<eb, 256>>>(ei);
    gelu1_kernel<<<(NN * C1 + 255) / 256, 256>>>(bias1);

    // 3) layer-2 transforms: xl2 = z1@W_l2+b_l2, xr2 = z1@W_r2+b_r2
    {
        dim3 grid(2 * (OUTC / 128), (NN + 127) / 128);
        gemm_dual<<<grid, 256>>>(out1, W_l2, W_r2, b_l2, b_r2, xl2, xr2, NN, C1, OUTC);
    }

    // 4) layer-2 attention
    logits2_kernel<<<eb, 256>>>(ei, att2);
    expsum2_kernel<<<(ET + 255) / 256, 256>>>(ei);
    scatter2_kernel<<<eb, 256>>>(ei);
    bias2_kernel<<<(NN * OUTC + 255) / 256, 256>>>(bias2);

    // 5) decoder
    {
        dim3 grid(1, (ELL + 127) / 128);
        gemm_dec<<<grid, 256>>>(out2, eli, W_d1, b_d1);
    }
    dec_reduce<<<((ELL * 32) + 255) / 256, 256>>>(W_d2, b_d2, out);
}